// round 13
// baseline (speedup 1.0000x reference)
#include <cuda_runtime.h>
#include <cstdint>

typedef unsigned long long u64;
typedef unsigned int u32;

#define G_DIM 2048
#define T_DIM 16
#define B_DIM 256
#define P_DIM 64

// Device-global scratch (no allocations allowed)
__device__ u64  g_pv[B_DIM];
__device__ int2 g_tlohi[G_DIM * T_DIM];  // packed bits (lo, hi) per (g,t)
__device__ int  g_pw[G_DIM * T_DIM];     // per-term weight (+-2^{8k} or 0)
__device__ int4 g_meta[G_DIM];           // x=s_pack, y=m0, z=m1|m2<<8|m3<<16
__device__ int4 g_T[3 * 17 * 17];        // (1+w^{k+1})^a (1-w^{k+1})^b

// ---------------------------------------------------------------------------
// Ring ops in basis (1, w, w^2, w^3), w^4 = -1.
// ---------------------------------------------------------------------------
__device__ __forceinline__ void ringmul(int* z, const int* x, const int* y) {
    z[0] = x[0]*y[0] - x[1]*y[3] - x[2]*y[2] - x[3]*y[1];
    z[1] = x[0]*y[1] + x[1]*y[0] - x[2]*y[3] - x[3]*y[2];
    z[2] = x[0]*y[2] + x[1]*y[1] + x[2]*y[0] - x[3]*y[3];
    z[3] = x[0]*y[3] + x[1]*y[2] + x[2]*y[1] + x[3]*y[0];
}
__device__ __forceinline__ void ringcpy(int* d, const int* s) {
    d[0] = s[0]; d[1] = s[1]; d[2] = s[2]; d[3] = s[3];
}
__device__ __forceinline__ void ringpow(int* acc, const int* f, int n) {
    int base[4], tmp[4];
    acc[0] = 1; acc[1] = 0; acc[2] = 0; acc[3] = 0;
    ringcpy(base, f);
    while (n) {
        if (n & 1) { ringmul(tmp, acc, base); ringcpy(acc, tmp); }
        n >>= 1;
        if (n) { ringmul(tmp, base, base); ringcpy(base, tmp); }
    }
}
__device__ __forceinline__ int clamp_cnt(int c) {
    return c < 0 ? 0 : (c > T_DIM ? T_DIM : c);
}

// ---------------------------------------------------------------------------
// Init: 261 blocks.
//   [0,256): pack params + per-g meta (8 g's per block, one warp per g)
//   [256,260): build g_T (867 entries, one per thread)
//   260: pack param_vals (8 warps x 32 rows)
// ---------------------------------------------------------------------------
__global__ void init_kernel(const int* __restrict__ params,
                            const int* __restrict__ phases,
                            const int* __restrict__ counts,
                            const int* __restrict__ param_vals) {
    const int bid  = blockIdx.x;
    const int tid  = threadIdx.x;
    const int lane = tid & 31;
    const int warp = tid >> 5;

    if (bid < 256) {
        const int g = bid * 8 + warp;
        const int* pr = params + (size_t)g * (T_DIM * P_DIM);
        // pack 16 rows in two batches of 8 (MLP)
        #pragma unroll
        for (int bt = 0; bt < 2; bt++) {
            int a[8], b[8];
            #pragma unroll
            for (int r = 0; r < 8; r++) {
                int row = bt * 8 + r;
                a[r] = pr[row * P_DIM + lane];
                b[r] = pr[row * P_DIM + 32 + lane];
            }
            #pragma unroll
            for (int r = 0; r < 8; r++) {
                u32 lo = __ballot_sync(0xffffffffu, a[r] & 1);
                u32 hi = __ballot_sync(0xffffffffu, b[r] & 1);
                if (lane == 0)
                    g_tlohi[g * T_DIM + bt * 8 + r] = make_int2((int)lo, (int)hi);
            }
        }
        // meta + pw
        int c = clamp_cnt(counts[g]);
        u32 vm = (c >= 16) ? 0xFFFFu : ((1u << c) - 1u);
        int p  = (lane < 16) ? (phases[g * T_DIM + lane] & 7) : 0;
        int k  = p & 3;
        int sg = (p >> 2) & 1;
        u32 b0m = __ballot_sync(0xffffffffu, k == 0) & vm;
        u32 b1m = __ballot_sync(0xffffffffu, k == 1) & vm;
        u32 b2m = __ballot_sync(0xffffffffu, k == 2) & vm;
        u32 b3m = __ballot_sync(0xffffffffu, k == 3) & vm;
        u32 sgm = __ballot_sync(0xffffffffu, sg == 1) & vm;
        if (lane < 16) {
            int valid = (vm >> lane) & 1;
            g_pw[g * T_DIM + lane] = valid ? (sg ? -(1 << (8 * k)) : (1 << (8 * k))) : 0;
        }
        if (lane == 0) {
            int s0 = __popc(b0m & sgm), s1 = __popc(b1m & sgm),
                s2 = __popc(b2m & sgm), s3 = __popc(b3m & sgm);
            int m1 = __popc(b1m), m2 = __popc(b2m), m3 = __popc(b3m);
            g_meta[g] = make_int4(s0 | (s1 << 8) | (s2 << 16) | (s3 << 24),
                                  __popc(b0m),
                                  m1 | (m2 << 8) | (m3 << 16), 0);
        }
    } else if (bid < 260) {
        int e = (bid - 256) * 256 + tid;
        if (e < 3 * 289) {
            int k = e / 289, r = e % 289, a = r / 17, b = r % 17;
            int4 o;
            if (a + b > 16) {
                o = make_int4(0, 0, 0, 0);
            } else {
                int kk = k + 1;
                int fp[4] = {1, 0, 0, 0}; fp[kk] = 1;
                int fm[4] = {1, 0, 0, 0}; fm[kk] = -1;
                int pa[4], pb[4], acc[4];
                ringpow(pa, fp, a);
                ringpow(pb, fm, b);
                ringmul(acc, pa, pb);
                o = make_int4(acc[0], acc[1], acc[2], acc[3]);
            }
            g_T[e] = o;
        }
    } else {
        // pv pack: warp w -> rows w*32 .. w*32+31, batches of 4
        #pragma unroll
        for (int bt = 0; bt < 8; bt++) {
            int row0 = warp * 32 + bt * 4;
            int a[4], b[4];
            #pragma unroll
            for (int r = 0; r < 4; r++) {
                const int* p = param_vals + (size_t)(row0 + r) * P_DIM;
                a[r] = p[lane]; b[r] = p[lane + 32];
            }
            #pragma unroll
            for (int r = 0; r < 4; r++) {
                u32 lo = __ballot_sync(0xffffffffu, a[r] & 1);
                u32 hi = __ballot_sync(0xffffffffu, b[r] & 1);
                if (lane == 0) g_pv[row0 + r] = ((u64)hi << 32) | (u64)lo;
            }
        }
    }
}

// ---------------------------------------------------------------------------
// Main: 1024 blocks x 256 threads. Block = 2 g's x all 256 b's; thread = one
// b x both g's. Thin prologue (pure loads, no ballots), one barrier; compute;
// smem-staged transposed stores (32B-contiguous chunks).
// Epilogue: R = A*C (16 IMAD), Z = R*B with B in Z[i] (8 IMAD). 2^m0 folded
// into class-1 rows at staging; zero-flag via float select.
// Output float32 (B, G, 4) in reference basis (1,w,w^2,w^7): c3 = -z3.
// ---------------------------------------------------------------------------
__global__ void __launch_bounds__(256, 6)
nodephases_main_kernel(float* __restrict__ out) {
    const int g0   = blockIdx.x * 2;
    const int tid  = threadIdx.x;
    const int lane = tid & 31;
    const int warp = tid >> 5;

    __shared__ int4   s_term[2][T_DIM];     // x=lo, y=hi, z=pw
    __shared__ int4   s_meta[2];
    __shared__ int4   s_rows[2][3][17];
    __shared__ float4 s_out[B_DIM][2];

    // ---- prologue: pure loads, no ballots ----
    if (tid < 16) {
        // terms lo/hi: LDG.128 covers 2 terms (2x int2)
        int4 v = ((const int4*)(g_tlohi + g0 * T_DIM))[tid];
        int r = tid * 2;
        s_term[r >> 4][r & 15].x = v.x;
        s_term[r >> 4][r & 15].y = v.y;
        s_term[(r + 1) >> 4][(r + 1) & 15].x = v.z;
        s_term[(r + 1) >> 4][(r + 1) & 15].y = v.w;
    } else if (tid < 24) {
        // pw: LDG.128 covers 4 ints
        int j = tid - 16;
        int4 w = ((const int4*)(g_pw + g0 * T_DIM))[j];
        int r = j * 4;
        s_term[r >> 4][r & 15].z = w.x;
        s_term[(r + 1) >> 4][(r + 1) & 15].z = w.y;
        s_term[(r + 2) >> 4][(r + 2) & 15].z = w.z;
        s_term[(r + 3) >> 4][(r + 3) & 15].z = w.w;
    } else if (tid < 26) {
        s_meta[tid - 24] = g_meta[g0 + (tid - 24)];
    }
    if (warp >= 2) {
        // rows: warp w covers (gi = (w-2)/3, class kk = (w-2)%3 + 1)
        int w  = warp - 2;
        int gi = w / 3;
        int kk = w % 3 + 1;
        int4 mt = g_meta[g0 + gi];
        int m  = (mt.z >> (8 * (kk - 1))) & 255;
        int m0 = mt.y;
        if (lane <= m) {
            int4 e = g_T[(kk - 1) * 289 + (m - lane) * 17 + lane];
            if (kk == 1) { e.x <<= m0; e.y <<= m0; e.z <<= m0; e.w <<= m0; }
            s_rows[gi][kk - 1][lane] = e;
        }
    }
    __syncthreads();

    // ---- compute: one b, two g's ----
    const u64 v = g_pv[tid];
    const u32 vlo = (u32)v, vhi = (u32)(v >> 32);

    #pragma unroll
    for (int gi = 0; gi < 2; gi++) {
        int cpA = s_meta[gi].x;
        int cpB = 0x10101010;
        #pragma unroll
        for (int t = 0; t < 8; t++) {
            int4 tw = s_term[gi][t];
            u32 x = ((u32)tw.x & vlo) ^ ((u32)tw.y & vhi);
            cpA += (int)(__popc(x) & 1u) * tw.z;
        }
        #pragma unroll
        for (int t = 8; t < 16; t++) {
            int4 tw = s_term[gi][t];
            u32 x = ((u32)tw.x & vlo) ^ ((u32)tw.y & vhi);
            cpB += (int)(__popc(x) & 1u) * tw.z;
        }
        int cp = cpA + cpB - 0x10101010;

        int b0 = cp & 255;
        int b1 = (cp >> 8) & 255;
        int b2 = (cp >> 16) & 255;
        int b3 = (cp >> 24) & 255;

        int4 A  = s_rows[gi][0][b1];   // class 1, pre-scaled by 2^m0
        int4 Bc = s_rows[gi][1][b2];   // class 2: only .x, .z nonzero
        int4 C  = s_rows[gi][2][b3];   // class 3

        int r0 = A.x*C.x - A.y*C.w - A.z*C.z - A.w*C.y;
        int r1 = A.x*C.y + A.y*C.x - A.z*C.w - A.w*C.z;
        int r2 = A.x*C.z + A.y*C.y + A.z*C.x - A.w*C.w;
        int r3 = A.x*C.w + A.y*C.z + A.z*C.y + A.w*C.x;

        int z0 = r0*Bc.x - r2*Bc.z;
        int z1 = r1*Bc.x - r3*Bc.z;
        int z2 = r2*Bc.x + r0*Bc.z;
        int z3 = r3*Bc.x + r1*Bc.z;

        bool nz = (b0 == 0);
        float f0 = nz ? (float)z0 : 0.0f;
        float f1 = nz ? (float)z1 : 0.0f;
        float f2 = nz ? (float)z2 : 0.0f;
        float f3 = nz ? (float)(-z3) : 0.0f;   // basis: c3_ref = -z3

        s_out[tid][gi] = make_float4(f0, f1, f2, f3);
    }
    __syncthreads();

    // ---- store phase: lane-consecutive (b, gs) -> 32B contiguous chunks ----
    float4* out4 = (float4*)out;
    #pragma unroll
    for (int r = 0; r < 2; r++) {
        int idx = tid + r * 256;
        int b  = idx >> 1;
        int gs = idx & 1;
        out4[(size_t)b * G_DIM + g0 + gs] = s_out[b][gs];
    }
}

// ---------------------------------------------------------------------------
// Launch. Inputs identified BY SIZE (ordering-proof):
//   phases 32768 | params 2097152 | counts 2048 | param_vals 16384 | opp 32
// ---------------------------------------------------------------------------
extern "C" void kernel_launch(void* const* d_in, const int* in_sizes, int n_in,
                              void* d_out, int out_size) {
    const int* phases = nullptr;
    const int* params = nullptr;
    const int* counts = nullptr;
    const int* param_vals = nullptr;

    for (int i = 0; i < n_in; i++) {
        switch (in_sizes[i]) {
            case G_DIM * T_DIM:         phases     = (const int*)d_in[i]; break;
            case G_DIM * T_DIM * P_DIM: params     = (const int*)d_in[i]; break;
            case G_DIM:                 counts     = (const int*)d_in[i]; break;
            case B_DIM * P_DIM:         param_vals = (const int*)d_in[i]; break;
            default: break;  // one_plus_phases (32 floats) — unused
        }
    }

    init_kernel<<<261, 256>>>(params, phases, counts, param_vals);
    nodephases_main_kernel<<<G_DIM / 2, 256>>>((float*)d_out);
}

// round 14
// speedup vs baseline: 1.0195x; 1.0195x over previous
#include <cuda_runtime.h>
#include <cstdint>

typedef unsigned long long u64;
typedef unsigned int u32;

#define G_DIM 2048
#define T_DIM 16
#define B_DIM 256
#define P_DIM 64

// Device-global scratch (no allocations allowed)
__device__ u64  g_pv[B_DIM];
__device__ int2 g_tlohi[G_DIM * T_DIM];  // packed bits (lo, hi) per (g,t)
__device__ int  g_pw[G_DIM * T_DIM];     // per-term weight (+-2^{8k} or 0)
__device__ int4 g_meta[G_DIM];           // x=s_pack, y=m0, z=m1|m2<<8|m3<<16
__device__ int4 g_T[3 * 17 * 17];        // (1+w^{k+1})^a (1-w^{k+1})^b

// ---------------------------------------------------------------------------
// Ring ops in basis (1, w, w^2, w^3), w^4 = -1.
// ---------------------------------------------------------------------------
__device__ __forceinline__ void ringmul(int* z, const int* x, const int* y) {
    z[0] = x[0]*y[0] - x[1]*y[3] - x[2]*y[2] - x[3]*y[1];
    z[1] = x[0]*y[1] + x[1]*y[0] - x[2]*y[3] - x[3]*y[2];
    z[2] = x[0]*y[2] + x[1]*y[1] + x[2]*y[0] - x[3]*y[3];
    z[3] = x[0]*y[3] + x[1]*y[2] + x[2]*y[1] + x[3]*y[0];
}
__device__ __forceinline__ void ringcpy(int* d, const int* s) {
    d[0] = s[0]; d[1] = s[1]; d[2] = s[2]; d[3] = s[3];
}
__device__ __forceinline__ void ringpow(int* acc, const int* f, int n) {
    int base[4], tmp[4];
    acc[0] = 1; acc[1] = 0; acc[2] = 0; acc[3] = 0;
    ringcpy(base, f);
    while (n) {
        if (n & 1) { ringmul(tmp, acc, base); ringcpy(acc, tmp); }
        n >>= 1;
        if (n) { ringmul(tmp, base, base); ringcpy(base, tmp); }
    }
}
__device__ __forceinline__ int clamp_cnt(int c) {
    return c < 0 ? 0 : (c > T_DIM ? T_DIM : c);
}

// ---------------------------------------------------------------------------
// Init: 1037 blocks.
//   [0,1024):    pack params rows — 8 warps x 4 rows per block (32768 rows)
//   [1024,1032): meta + pw — one THREAD per g (no ballots, int4 loads/stores)
//   [1032,1036): build g_T (867 entries, one per thread)
//   1036:        pack param_vals (8 warps x 32 rows)
// ---------------------------------------------------------------------------
__global__ void init_kernel(const int* __restrict__ params,
                            const int* __restrict__ phases,
                            const int* __restrict__ counts,
                            const int* __restrict__ param_vals) {
    const int bid  = blockIdx.x;
    const int tid  = threadIdx.x;
    const int lane = tid & 31;
    const int warp = tid >> 5;

    if (bid < 1024) {                     // ---- params pack ----
        int row0 = bid * 32 + warp * 4;
        const int* pr = params + (size_t)row0 * P_DIM;
        int a[4], b[4];
        #pragma unroll
        for (int r = 0; r < 4; r++) {
            a[r] = pr[r * P_DIM + lane];
            b[r] = pr[r * P_DIM + 32 + lane];
        }
        #pragma unroll
        for (int r = 0; r < 4; r++) {
            u32 lo = __ballot_sync(0xffffffffu, a[r] & 1);
            u32 hi = __ballot_sync(0xffffffffu, b[r] & 1);
            if (lane == 0)
                g_tlohi[row0 + r] = make_int2((int)lo, (int)hi);
        }
    } else if (bid < 1032) {              // ---- meta + pw: thread per g ----
        int g = (bid - 1024) * 256 + tid;
        int c = clamp_cnt(counts[g]);

        const int4* ph4 = (const int4*)(phases + g * T_DIM);
        int4 pa = ph4[0], pb = ph4[1], pc = ph4[2], pd = ph4[3];
        int p[16] = { pa.x, pa.y, pa.z, pa.w, pb.x, pb.y, pb.z, pb.w,
                      pc.x, pc.y, pc.z, pc.w, pd.x, pd.y, pd.z, pd.w };

        int pw[16];
        int s0 = 0, s1 = 0, s2 = 0, s3 = 0;
        int m0 = 0, m1 = 0, m2 = 0, m3 = 0;
        #pragma unroll
        for (int t = 0; t < T_DIM; t++) {
            int pp = p[t] & 7;
            int k  = pp & 3;
            int sg = (pp >> 2) & 1;
            int valid = (t < c) ? 1 : 0;
            pw[t] = valid ? (sg ? -(1 << (8 * k)) : (1 << (8 * k))) : 0;
            int vs = valid & sg;
            s0 += vs & (k == 0); s1 += vs & (k == 1);
            s2 += vs & (k == 2); s3 += vs & (k == 3);
            m0 += valid & (k == 0); m1 += valid & (k == 1);
            m2 += valid & (k == 2); m3 += valid & (k == 3);
        }
        int4* pw4 = (int4*)(g_pw + g * T_DIM);
        pw4[0] = make_int4(pw[0],  pw[1],  pw[2],  pw[3]);
        pw4[1] = make_int4(pw[4],  pw[5],  pw[6],  pw[7]);
        pw4[2] = make_int4(pw[8],  pw[9],  pw[10], pw[11]);
        pw4[3] = make_int4(pw[12], pw[13], pw[14], pw[15]);
        g_meta[g] = make_int4(s0 | (s1 << 8) | (s2 << 16) | (s3 << 24),
                              m0, m1 | (m2 << 8) | (m3 << 16), 0);
    } else if (bid < 1036) {              // ---- g_T ----
        int e = (bid - 1032) * 256 + tid;
        if (e < 3 * 289) {
            int k = e / 289, r = e % 289, a = r / 17, b = r % 17;
            int4 o;
            if (a + b > 16) {
                o = make_int4(0, 0, 0, 0);
            } else {
                int kk = k + 1;
                int fp[4] = {1, 0, 0, 0}; fp[kk] = 1;
                int fm[4] = {1, 0, 0, 0}; fm[kk] = -1;
                int pa2[4], pb2[4], acc[4];
                ringpow(pa2, fp, a);
                ringpow(pb2, fm, b);
                ringmul(acc, pa2, pb2);
                o = make_int4(acc[0], acc[1], acc[2], acc[3]);
            }
            g_T[e] = o;
        }
    } else {                              // ---- pv pack ----
        #pragma unroll
        for (int bt = 0; bt < 8; bt++) {
            int row0 = warp * 32 + bt * 4;
            int a[4], b[4];
            #pragma unroll
            for (int r = 0; r < 4; r++) {
                const int* p = param_vals + (size_t)(row0 + r) * P_DIM;
                a[r] = p[lane]; b[r] = p[lane + 32];
            }
            #pragma unroll
            for (int r = 0; r < 4; r++) {
                u32 lo = __ballot_sync(0xffffffffu, a[r] & 1);
                u32 hi = __ballot_sync(0xffffffffu, b[r] & 1);
                if (lane == 0) g_pv[row0 + r] = ((u64)hi << 32) | (u64)lo;
            }
        }
    }
}

// ---------------------------------------------------------------------------
// Main: 1024 blocks x 256 threads. Block = 2 g's x all 256 b's; thread = one
// b x both g's. Thin prologue (pure loads, no ballots), one barrier; compute;
// smem-staged transposed stores (32B-contiguous chunks).
// Epilogue: R = A*C (16 IMAD), Z = R*B with B in Z[i] (8 IMAD). 2^m0 folded
// into class-1 rows at staging; zero-flag via float select.
// Output float32 (B, G, 4) in reference basis (1,w,w^2,w^7): c3 = -z3.
// ---------------------------------------------------------------------------
__global__ void __launch_bounds__(256, 6)
nodephases_main_kernel(float* __restrict__ out) {
    const int g0   = blockIdx.x * 2;
    const int tid  = threadIdx.x;
    const int lane = tid & 31;
    const int warp = tid >> 5;

    __shared__ int4   s_term[2][T_DIM];     // x=lo, y=hi, z=pw
    __shared__ int4   s_meta[2];
    __shared__ int4   s_rows[2][3][17];
    __shared__ float4 s_out[B_DIM][2];

    // ---- prologue: pure loads, no ballots ----
    if (tid < 16) {
        int4 v = ((const int4*)(g_tlohi + g0 * T_DIM))[tid];
        int r = tid * 2;
        s_term[r >> 4][r & 15].x = v.x;
        s_term[r >> 4][r & 15].y = v.y;
        s_term[(r + 1) >> 4][(r + 1) & 15].x = v.z;
        s_term[(r + 1) >> 4][(r + 1) & 15].y = v.w;
    } else if (tid < 24) {
        int j = tid - 16;
        int4 w = ((const int4*)(g_pw + g0 * T_DIM))[j];
        int r = j * 4;
        s_term[r >> 4][r & 15].z = w.x;
        s_term[(r + 1) >> 4][(r + 1) & 15].z = w.y;
        s_term[(r + 2) >> 4][(r + 2) & 15].z = w.z;
        s_term[(r + 3) >> 4][(r + 3) & 15].z = w.w;
    } else if (tid < 26) {
        s_meta[tid - 24] = g_meta[g0 + (tid - 24)];
    }
    if (warp >= 2) {
        int w  = warp - 2;
        int gi = w / 3;
        int kk = w % 3 + 1;
        int4 mt = g_meta[g0 + gi];
        int m  = (mt.z >> (8 * (kk - 1))) & 255;
        int m0 = mt.y;
        if (lane <= m) {
            int4 e = g_T[(kk - 1) * 289 + (m - lane) * 17 + lane];
            if (kk == 1) { e.x <<= m0; e.y <<= m0; e.z <<= m0; e.w <<= m0; }
            s_rows[gi][kk - 1][lane] = e;
        }
    }
    __syncthreads();

    // ---- compute: one b, two g's ----
    const u64 v = g_pv[tid];
    const u32 vlo = (u32)v, vhi = (u32)(v >> 32);

    #pragma unroll
    for (int gi = 0; gi < 2; gi++) {
        int cpA = s_meta[gi].x;
        int cpB = 0x10101010;
        #pragma unroll
        for (int t = 0; t < 8; t++) {
            int4 tw = s_term[gi][t];
            u32 x = ((u32)tw.x & vlo) ^ ((u32)tw.y & vhi);
            cpA += (int)(__popc(x) & 1u) * tw.z;
        }
        #pragma unroll
        for (int t = 8; t < 16; t++) {
            int4 tw = s_term[gi][t];
            u32 x = ((u32)tw.x & vlo) ^ ((u32)tw.y & vhi);
            cpB += (int)(__popc(x) & 1u) * tw.z;
        }
        int cp = cpA + cpB - 0x10101010;

        int b0 = cp & 255;
        int b1 = (cp >> 8) & 255;
        int b2 = (cp >> 16) & 255;
        int b3 = (cp >> 24) & 255;

        int4 A  = s_rows[gi][0][b1];   // class 1, pre-scaled by 2^m0
        int4 Bc = s_rows[gi][1][b2];   // class 2: only .x, .z nonzero
        int4 C  = s_rows[gi][2][b3];   // class 3

        int r0 = A.x*C.x - A.y*C.w - A.z*C.z - A.w*C.y;
        int r1 = A.x*C.y + A.y*C.x - A.z*C.w - A.w*C.z;
        int r2 = A.x*C.z + A.y*C.y + A.z*C.x - A.w*C.w;
        int r3 = A.x*C.w + A.y*C.z + A.z*C.y + A.w*C.x;

        int z0 = r0*Bc.x - r2*Bc.z;
        int z1 = r1*Bc.x - r3*Bc.z;
        int z2 = r2*Bc.x + r0*Bc.z;
        int z3 = r3*Bc.x + r1*Bc.z;

        bool nz = (b0 == 0);
        float f0 = nz ? (float)z0 : 0.0f;
        float f1 = nz ? (float)z1 : 0.0f;
        float f2 = nz ? (float)z2 : 0.0f;
        float f3 = nz ? (float)(-z3) : 0.0f;   // basis: c3_ref = -z3

        s_out[tid][gi] = make_float4(f0, f1, f2, f3);
    }
    __syncthreads();

    // ---- store phase: lane-consecutive (b, gs) -> 32B contiguous chunks ----
    float4* out4 = (float4*)out;
    #pragma unroll
    for (int r = 0; r < 2; r++) {
        int idx = tid + r * 256;
        int b  = idx >> 1;
        int gs = idx & 1;
        out4[(size_t)b * G_DIM + g0 + gs] = s_out[b][gs];
    }
}

// ---------------------------------------------------------------------------
// Launch. Inputs identified BY SIZE (ordering-proof):
//   phases 32768 | params 2097152 | counts 2048 | param_vals 16384 | opp 32
// ---------------------------------------------------------------------------
extern "C" void kernel_launch(void* const* d_in, const int* in_sizes, int n_in,
                              void* d_out, int out_size) {
    const int* phases = nullptr;
    const int* params = nullptr;
    const int* counts = nullptr;
    const int* param_vals = nullptr;

    for (int i = 0; i < n_in; i++) {
        switch (in_sizes[i]) {
            case G_DIM * T_DIM:         phases     = (const int*)d_in[i]; break;
            case G_DIM * T_DIM * P_DIM: params     = (const int*)d_in[i]; break;
            case G_DIM:                 counts     = (const int*)d_in[i]; break;
            case B_DIM * P_DIM:         param_vals = (const int*)d_in[i]; break;
            default: break;  // one_plus_phases (32 floats) — unused
        }
    }

    init_kernel<<<1037, 256>>>(params, phases, counts, param_vals);
    nodephases_main_kernel<<<G_DIM / 2, 256>>>((float*)d_out);
}

// round 15
// speedup vs baseline: 1.0467x; 1.0267x over previous
#include <cuda_runtime.h>
#include <cstdint>

typedef unsigned long long u64;
typedef unsigned int u32;

#define G_DIM 2048
#define T_DIM 16
#define B_DIM 256
#define P_DIM 64

// Device-global scratch (no allocations allowed)
__device__ u64  g_pv[B_DIM];
__device__ int4 g_T[3 * 17 * 17];   // (1+w^{k+1})^a (1-w^{k+1})^b, a+b<=16

// ---------------------------------------------------------------------------
// Ring ops in basis (1, w, w^2, w^3), w^4 = -1.
// ---------------------------------------------------------------------------
__device__ __forceinline__ void ringmul(int* z, const int* x, const int* y) {
    z[0] = x[0]*y[0] - x[1]*y[3] - x[2]*y[2] - x[3]*y[1];
    z[1] = x[0]*y[1] + x[1]*y[0] - x[2]*y[3] - x[3]*y[2];
    z[2] = x[0]*y[2] + x[1]*y[1] + x[2]*y[0] - x[3]*y[3];
    z[3] = x[0]*y[3] + x[1]*y[2] + x[2]*y[1] + x[3]*y[0];
}
__device__ __forceinline__ void ringcpy(int* d, const int* s) {
    d[0] = s[0]; d[1] = s[1]; d[2] = s[2]; d[3] = s[3];
}
__device__ __forceinline__ void ringpow(int* acc, const int* f, int n) {
    int base[4], tmp[4];
    acc[0] = 1; acc[1] = 0; acc[2] = 0; acc[3] = 0;
    ringcpy(base, f);
    while (n) {
        if (n & 1) { ringmul(tmp, acc, base); ringcpy(acc, tmp); }
        n >>= 1;
        if (n) { ringmul(tmp, base, base); ringcpy(base, tmp); }
    }
}
__device__ __forceinline__ int clamp_cnt(int c) {
    return c < 0 ? 0 : (c > T_DIM ? T_DIM : c);
}

// ---------------------------------------------------------------------------
// Init: 12 blocks. Blocks 0..3 build g_T (867 entries, one per thread).
// Blocks 4..11 pack param_vals (8 warps x 4 rows each = 32 rows/block).
// ---------------------------------------------------------------------------
__global__ void init_kernel(const int* __restrict__ param_vals) {
    if (blockIdx.x < 4) {
        int e = blockIdx.x * 256 + threadIdx.x;
        if (e < 3 * 289) {
            int k = e / 289, r = e % 289, a = r / 17, b = r % 17;
            int4 o;
            if (a + b > 16) {
                o = make_int4(0, 0, 0, 0);
            } else {
                int kk = k + 1;
                int fp[4] = {1, 0, 0, 0}; fp[kk] = 1;
                int fm[4] = {1, 0, 0, 0}; fm[kk] = -1;
                int pa[4], pb[4], acc[4];
                ringpow(pa, fp, a);
                ringpow(pb, fm, b);
                ringmul(acc, pa, pb);
                o = make_int4(acc[0], acc[1], acc[2], acc[3]);
            }
            g_T[e] = o;
        }
    } else {
        int warp = threadIdx.x >> 5, lane = threadIdx.x & 31;
        int row0 = ((blockIdx.x - 4) * 8 + warp) * 4;
        int a[4], b[4];
        #pragma unroll
        for (int r = 0; r < 4; r++) {
            const int* p = param_vals + (size_t)(row0 + r) * P_DIM;
            a[r] = p[lane]; b[r] = p[lane + 32];
        }
        #pragma unroll
        for (int r = 0; r < 4; r++) {
            u32 lo = __ballot_sync(0xffffffffu, a[r] & 1);
            u32 hi = __ballot_sync(0xffffffffu, b[r] & 1);
            if (lane == 0) g_pv[row0 + r] = ((u64)hi << 32) | (u64)lo;
        }
    }
}

// ---------------------------------------------------------------------------
// Main: 1024 blocks x 256 threads. Block = 2 g's x all 256 b's; thread = one
// b x both g's. Fused prologue (ONE barrier):
//   all 8 warps: ballot-pack 4 of the 32 param rows each into s_term.{x,y}
//   warps 0,1:  meta for g0+warp (s_pack, m0) + per-term pw -> s_term[..].z
//   warps 2..7: (gi,kk) = ((w-2)/3, (w-2)%3+1): re-ballot class mask, copy
//               row entries b=0..m from g_T (class-1 rows pre-scaled by 2^m0).
// Epilogue: R = A*C (16 IMAD), Z = R*B with class-2 B in Z[i] (8 IMAD);
// zero-flag via float select. Stores staged in smem, transposed so warps
// write 32B-contiguous (b, g-pair) chunks.
// Output float32 (B, G, 4) in reference basis (1,w,w^2,w^7): c3 = -z3.
// ---------------------------------------------------------------------------
__global__ void __launch_bounds__(256, 6)
nodephases_main_kernel(const int* __restrict__ params,
                       const int* __restrict__ phases,
                       const int* __restrict__ counts,
                       float* __restrict__ out) {
    const int g0   = blockIdx.x * 2;
    const int tid  = threadIdx.x;
    const int lane = tid & 31;
    const int warp = tid >> 5;

    __shared__ int4   s_term[2][T_DIM];     // x=lo, y=hi, z=pw
    __shared__ int2   s_meta[2];            // x=s_pack, y=m0
    __shared__ int4   s_rows[2][3][17];
    __shared__ float4 s_out[B_DIM][2];

    // ---- pack: warp w -> rows w*4 .. w*4+3 (row = gi*16 + t) ----
    {
        const int row0 = warp * 4;
        const int* basep = params + ((size_t)g0 * T_DIM + row0) * P_DIM;
        int a[4], b[4];
        #pragma unroll
        for (int r = 0; r < 4; r++) {
            a[r] = basep[r * P_DIM + lane];
            b[r] = basep[r * P_DIM + 32 + lane];
        }
        #pragma unroll
        for (int r = 0; r < 4; r++) {
            u32 lo = __ballot_sync(0xffffffffu, a[r] & 1);
            u32 hi = __ballot_sync(0xffffffffu, b[r] & 1);
            if (lane == 0) {
                int row = row0 + r;
                s_term[row >> 4][row & 15].x = (int)lo;
                s_term[row >> 4][row & 15].y = (int)hi;
            }
        }
    }

    // ---- role work (no cross-warp dependencies; one barrier after) ----
    if (warp < 2) {
        // meta + pw for g = g0 + warp
        const int gi = warp;
        const int g  = g0 + gi;
        int c = clamp_cnt(counts[g]);
        u32 vm = (c >= 16) ? 0xFFFFu : ((1u << c) - 1u);
        int p  = (lane < 16) ? (phases[g * T_DIM + lane] & 7) : 0;
        int k  = p & 3;
        int sg = (p >> 2) & 1;
        u32 b0m = __ballot_sync(0xffffffffu, k == 0) & vm;
        u32 b1m = __ballot_sync(0xffffffffu, k == 1) & vm;
        u32 b2m = __ballot_sync(0xffffffffu, k == 2) & vm;
        u32 b3m = __ballot_sync(0xffffffffu, k == 3) & vm;
        u32 sgm = __ballot_sync(0xffffffffu, sg == 1) & vm;
        if (lane < 16) {
            int valid = (vm >> lane) & 1;
            s_term[gi][lane].z = valid ? (sg ? -(1 << (8 * k)) : (1 << (8 * k))) : 0;
        }
        if (lane == 0) {
            int s0 = __popc(b0m & sgm), s1 = __popc(b1m & sgm),
                s2 = __popc(b2m & sgm), s3 = __popc(b3m & sgm);
            s_meta[gi] = make_int2(s0 | (s1 << 8) | (s2 << 16) | (s3 << 24),
                                   __popc(b0m));
        }
    } else {
        // rows: warp w covers (gi = (w-2)/3, class kk = (w-2)%3 + 1)
        const int w  = warp - 2;
        const int gi = w / 3;
        const int kk = w % 3 + 1;
        const int g  = g0 + gi;
        int c = clamp_cnt(counts[g]);
        u32 vm = (c >= 16) ? 0xFFFFu : ((1u << c) - 1u);
        int p  = (lane < 16) ? (phases[g * T_DIM + lane] & 7) : 0;
        u32 km  = __ballot_sync(0xffffffffu, ((p & 3) == kk) && (lane < 16)) & vm;
        u32 b0m = __ballot_sync(0xffffffffu, ((p & 3) == 0)  && (lane < 16)) & vm;
        int m  = __popc(km);
        int m0 = __popc(b0m);
        if (lane <= m) {
            int4 e = __ldg(&g_T[(kk - 1) * 289 + (m - lane) * 17 + lane]);
            if (kk == 1) { e.x <<= m0; e.y <<= m0; e.z <<= m0; e.w <<= m0; }
            s_rows[gi][kk - 1][lane] = e;
        }
    }
    __syncthreads();

    // ---- compute: one b, two g's ----
    const u64 v = g_pv[tid];
    const u32 vlo = (u32)v, vhi = (u32)(v >> 32);

    #pragma unroll
    for (int gi = 0; gi < 2; gi++) {
        int cpA = s_meta[gi].x;
        int cpB = 0x10101010;
        #pragma unroll
        for (int t = 0; t < 8; t++) {
            int4 tw = s_term[gi][t];
            u32 x = ((u32)tw.x & vlo) ^ ((u32)tw.y & vhi);
            cpA += (int)(__popc(x) & 1u) * tw.z;
        }
        #pragma unroll
        for (int t = 8; t < 16; t++) {
            int4 tw = s_term[gi][t];
            u32 x = ((u32)tw.x & vlo) ^ ((u32)tw.y & vhi);
            cpB += (int)(__popc(x) & 1u) * tw.z;
        }
        int cp = cpA + cpB - 0x10101010;

        int b0 = cp & 255;
        int b1 = (cp >> 8) & 255;
        int b2 = (cp >> 16) & 255;
        int b3 = (cp >> 24) & 255;

        int4 A  = s_rows[gi][0][b1];   // class 1, pre-scaled by 2^m0
        int4 Bc = s_rows[gi][1][b2];   // class 2: only .x, .z nonzero
        int4 C  = s_rows[gi][2][b3];   // class 3

        int r0 = A.x*C.x - A.y*C.w - A.z*C.z - A.w*C.y;
        int r1 = A.x*C.y + A.y*C.x - A.z*C.w - A.w*C.z;
        int r2 = A.x*C.z + A.y*C.y + A.z*C.x - A.w*C.w;
        int r3 = A.x*C.w + A.y*C.z + A.z*C.y + A.w*C.x;

        int z0 = r0*Bc.x - r2*Bc.z;
        int z1 = r1*Bc.x - r3*Bc.z;
        int z2 = r2*Bc.x + r0*Bc.z;
        int z3 = r3*Bc.x + r1*Bc.z;

        bool nz = (b0 == 0);
        float f0 = nz ? (float)z0 : 0.0f;
        float f1 = nz ? (float)z1 : 0.0f;
        float f2 = nz ? (float)z2 : 0.0f;
        float f3 = nz ? (float)(-z3) : 0.0f;   // basis: c3_ref = -z3

        s_out[tid][gi] = make_float4(f0, f1, f2, f3);
    }
    __syncthreads();

    // ---- store phase: lane-consecutive (b, gs) -> 32B contiguous chunks ----
    float4* out4 = (float4*)out;
    #pragma unroll
    for (int r = 0; r < 2; r++) {
        int idx = tid + r * 256;
        int b  = idx >> 1;
        int gs = idx & 1;
        out4[(size_t)b * G_DIM + g0 + gs] = s_out[b][gs];
    }
}

// ---------------------------------------------------------------------------
// Launch. Inputs identified BY SIZE (ordering-proof):
//   phases 32768 | params 2097152 | counts 2048 | param_vals 16384 | opp 32
// ---------------------------------------------------------------------------
extern "C" void kernel_launch(void* const* d_in, const int* in_sizes, int n_in,
                              void* d_out, int out_size) {
    const int* phases = nullptr;
    const int* params = nullptr;
    const int* counts = nullptr;
    const int* param_vals = nullptr;

    for (int i = 0; i < n_in; i++) {
        switch (in_sizes[i]) {
            case G_DIM * T_DIM:         phases     = (const int*)d_in[i]; break;
            case G_DIM * T_DIM * P_DIM: params     = (const int*)d_in[i]; break;
            case G_DIM:                 counts     = (const int*)d_in[i]; break;
            case B_DIM * P_DIM:         param_vals = (const int*)d_in[i]; break;
            default: break;  // one_plus_phases (32 floats) — unused
        }
    }

    init_kernel<<<12, 256>>>(param_vals);
    nodephases_main_kernel<<<G_DIM / 2, 256>>>(params, phases, counts,
                                               (float*)d_out);
}

// round 16
// speedup vs baseline: 1.1572x; 1.1057x over previous
#include <cuda_runtime.h>
#include <cstdint>

typedef unsigned long long u64;
typedef unsigned int u32;

#define G_DIM 2048
#define T_DIM 16
#define B_DIM 256
#define P_DIM 64

// Device-global scratch (no allocations allowed)
__device__ u64  g_pv[B_DIM];
__device__ int4 g_T[3 * 17 * 17];   // (1+w^{k+1})^a (1-w^{k+1})^b, a+b<=16

// ---------------------------------------------------------------------------
// Ring ops in basis (1, w, w^2, w^3), w^4 = -1.
// ---------------------------------------------------------------------------
__device__ __forceinline__ void ringmul(int* z, const int* x, const int* y) {
    z[0] = x[0]*y[0] - x[1]*y[3] - x[2]*y[2] - x[3]*y[1];
    z[1] = x[0]*y[1] + x[1]*y[0] - x[2]*y[3] - x[3]*y[2];
    z[2] = x[0]*y[2] + x[1]*y[1] + x[2]*y[0] - x[3]*y[3];
    z[3] = x[0]*y[3] + x[1]*y[2] + x[2]*y[1] + x[3]*y[0];
}
__device__ __forceinline__ void ringcpy(int* d, const int* s) {
    d[0] = s[0]; d[1] = s[1]; d[2] = s[2]; d[3] = s[3];
}
__device__ __forceinline__ void ringpow(int* acc, const int* f, int n) {
    int base[4], tmp[4];
    acc[0] = 1; acc[1] = 0; acc[2] = 0; acc[3] = 0;
    ringcpy(base, f);
    while (n) {
        if (n & 1) { ringmul(tmp, acc, base); ringcpy(acc, tmp); }
        n >>= 1;
        if (n) { ringmul(tmp, base, base); ringcpy(base, tmp); }
    }
}
__device__ __forceinline__ int clamp_cnt(int c) {
    return c < 0 ? 0 : (c > T_DIM ? T_DIM : c);
}

// ---------------------------------------------------------------------------
// Init: 12 blocks. Blocks 0..3 build g_T (867 entries, one per thread).
// Blocks 4..11 pack param_vals (8 warps x 4 rows each = 32 rows/block).
// ---------------------------------------------------------------------------
__global__ void init_kernel(const int* __restrict__ param_vals) {
    if (blockIdx.x < 4) {
        int e = blockIdx.x * 256 + threadIdx.x;
        if (e < 3 * 289) {
            int k = e / 289, r = e % 289, a = r / 17, b = r % 17;
            int4 o;
            if (a + b > 16) {
                o = make_int4(0, 0, 0, 0);
            } else {
                int kk = k + 1;
                int fp[4] = {1, 0, 0, 0}; fp[kk] = 1;
                int fm[4] = {1, 0, 0, 0}; fm[kk] = -1;
                int pa[4], pb[4], acc[4];
                ringpow(pa, fp, a);
                ringpow(pb, fm, b);
                ringmul(acc, pa, pb);
                o = make_int4(acc[0], acc[1], acc[2], acc[3]);
            }
            g_T[e] = o;
        }
    } else {
        int warp = threadIdx.x >> 5, lane = threadIdx.x & 31;
        int row0 = ((blockIdx.x - 4) * 8 + warp) * 4;
        int a[4], b[4];
        #pragma unroll
        for (int r = 0; r < 4; r++) {
            const int* p = param_vals + (size_t)(row0 + r) * P_DIM;
            a[r] = p[lane]; b[r] = p[lane + 32];
        }
        #pragma unroll
        for (int r = 0; r < 4; r++) {
            u32 lo = __ballot_sync(0xffffffffu, a[r] & 1);
            u32 hi = __ballot_sync(0xffffffffu, b[r] & 1);
            if (lane == 0) g_pv[row0 + r] = ((u64)hi << 32) | (u64)lo;
        }
    }
}

// ---------------------------------------------------------------------------
// Main: 1024 blocks x 128 threads (4 warps). Block = 2 g's x 256 b's;
// thread = 2 b's (tid, tid+128) x both g's — term LDS shared across b's.
// Prologue (ONE barrier):
//   all 4 warps: ballot-pack 8 of the 32 param rows each into s_term.{x,y}
//   warp 0,1: meta for g0+warp (s_pack, m0) + per-term pw -> s_term[..].z
//   warp 2,3: gi = warp-2; for kk=1..3 re-ballot class mask, copy row
//             entries b=0..m from g_T (class-1 rows pre-scaled by 2^m0).
// Epilogue: R = A*C (16 IMAD), Z = R*B with class-2 B in Z[i] (8 IMAD);
// zero-flag via float select. Stores staged in smem, transposed to
// 32B-contiguous (b, g-pair) chunks.
// Output float32 (B, G, 4) in reference basis (1,w,w^2,w^7): c3 = -z3.
// ---------------------------------------------------------------------------
__global__ void __launch_bounds__(128)
nodephases_main_kernel(const int* __restrict__ params,
                       const int* __restrict__ phases,
                       const int* __restrict__ counts,
                       float* __restrict__ out) {
    const int g0   = blockIdx.x * 2;
    const int tid  = threadIdx.x;
    const int lane = tid & 31;
    const int warp = tid >> 5;

    __shared__ int4   s_term[2][T_DIM];     // x=lo, y=hi, z=pw
    __shared__ int2   s_meta[2];            // x=s_pack, y=m0
    __shared__ int4   s_rows[2][3][17];
    __shared__ float4 s_out[B_DIM][2];

    // ---- pack: warp w -> rows w*8 .. w*8+7 (row = gi*16 + t) ----
    {
        const int row0 = warp * 8;
        const int* basep = params + ((size_t)g0 * T_DIM + row0) * P_DIM;
        int a[8], b[8];
        #pragma unroll
        for (int r = 0; r < 8; r++) {
            a[r] = basep[r * P_DIM + lane];
            b[r] = basep[r * P_DIM + 32 + lane];
        }
        #pragma unroll
        for (int r = 0; r < 8; r++) {
            u32 lo = __ballot_sync(0xffffffffu, a[r] & 1);
            u32 hi = __ballot_sync(0xffffffffu, b[r] & 1);
            if (lane == 0) {
                int row = row0 + r;
                s_term[row >> 4][row & 15].x = (int)lo;
                s_term[row >> 4][row & 15].y = (int)hi;
            }
        }
    }

    // ---- role work (no cross-warp dependencies; one barrier after) ----
    if (warp < 2) {
        // meta + pw for g = g0 + warp
        const int gi = warp;
        const int g  = g0 + gi;
        int c = clamp_cnt(counts[g]);
        u32 vm = (c >= 16) ? 0xFFFFu : ((1u << c) - 1u);
        int p  = (lane < 16) ? (phases[g * T_DIM + lane] & 7) : 0;
        int k  = p & 3;
        int sg = (p >> 2) & 1;
        u32 b0m = __ballot_sync(0xffffffffu, k == 0) & vm;
        u32 b1m = __ballot_sync(0xffffffffu, k == 1) & vm;
        u32 b2m = __ballot_sync(0xffffffffu, k == 2) & vm;
        u32 b3m = __ballot_sync(0xffffffffu, k == 3) & vm;
        u32 sgm = __ballot_sync(0xffffffffu, sg == 1) & vm;
        if (lane < 16) {
            int valid = (vm >> lane) & 1;
            s_term[gi][lane].z = valid ? (sg ? -(1 << (8 * k)) : (1 << (8 * k))) : 0;
        }
        if (lane == 0) {
            int s0 = __popc(b0m & sgm), s1 = __popc(b1m & sgm),
                s2 = __popc(b2m & sgm), s3 = __popc(b3m & sgm);
            s_meta[gi] = make_int2(s0 | (s1 << 8) | (s2 << 16) | (s3 << 24),
                                   __popc(b0m));
        }
    } else {
        // rows for g = g0 + (warp-2): 3 classes serially
        const int gi = warp - 2;
        const int g  = g0 + gi;
        int c = clamp_cnt(counts[g]);
        u32 vm = (c >= 16) ? 0xFFFFu : ((1u << c) - 1u);
        int p  = (lane < 16) ? (phases[g * T_DIM + lane] & 7) : 0;
        u32 b0m = __ballot_sync(0xffffffffu, ((p & 3) == 0) && (lane < 16)) & vm;
        int m0 = __popc(b0m);
        #pragma unroll
        for (int kk = 1; kk <= 3; kk++) {
            u32 km = __ballot_sync(0xffffffffu, ((p & 3) == kk) && (lane < 16)) & vm;
            int m = __popc(km);
            if (lane <= m) {
                int4 e = __ldg(&g_T[(kk - 1) * 289 + (m - lane) * 17 + lane]);
                if (kk == 1) { e.x <<= m0; e.y <<= m0; e.z <<= m0; e.w <<= m0; }
                s_rows[gi][kk - 1][lane] = e;
            }
        }
    }
    __syncthreads();

    // ---- compute: 2 b's x 2 g's per thread ----
    const u64 va = g_pv[tid];
    const u64 vb = g_pv[tid + 128];
    const u32 va_lo = (u32)va, va_hi = (u32)(va >> 32);
    const u32 vb_lo = (u32)vb, vb_hi = (u32)(vb >> 32);

    #pragma unroll
    for (int gi = 0; gi < 2; gi++) {
        const int2 meta = s_meta[gi];

        int cpA0 = meta.x, cpB0 = 0x10101010;
        int cpA1 = meta.x, cpB1 = 0x10101010;
        #pragma unroll
        for (int t = 0; t < 8; t++) {
            int4 tw = s_term[gi][t];
            u32 x0 = ((u32)tw.x & va_lo) ^ ((u32)tw.y & va_hi);
            u32 x1 = ((u32)tw.x & vb_lo) ^ ((u32)tw.y & vb_hi);
            cpA0 += (int)(__popc(x0) & 1u) * tw.z;
            cpA1 += (int)(__popc(x1) & 1u) * tw.z;
        }
        #pragma unroll
        for (int t = 8; t < 16; t++) {
            int4 tw = s_term[gi][t];
            u32 x0 = ((u32)tw.x & va_lo) ^ ((u32)tw.y & va_hi);
            u32 x1 = ((u32)tw.x & vb_lo) ^ ((u32)tw.y & vb_hi);
            cpB0 += (int)(__popc(x0) & 1u) * tw.z;
            cpB1 += (int)(__popc(x1) & 1u) * tw.z;
        }

        const int cp[2] = { cpA0 + cpB0 - 0x10101010, cpA1 + cpB1 - 0x10101010 };
        const int bsel[2] = { tid, tid + 128 };

        #pragma unroll
        for (int j = 0; j < 2; j++) {
            int b0 = cp[j] & 255;
            int b1 = (cp[j] >> 8) & 255;
            int b2 = (cp[j] >> 16) & 255;
            int b3 = (cp[j] >> 24) & 255;

            int4 A  = s_rows[gi][0][b1];   // class 1, pre-scaled by 2^m0
            int4 Bc = s_rows[gi][1][b2];   // class 2: only .x, .z nonzero
            int4 C  = s_rows[gi][2][b3];   // class 3

            int r0 = A.x*C.x - A.y*C.w - A.z*C.z - A.w*C.y;
            int r1 = A.x*C.y + A.y*C.x - A.z*C.w - A.w*C.z;
            int r2 = A.x*C.z + A.y*C.y + A.z*C.x - A.w*C.w;
            int r3 = A.x*C.w + A.y*C.z + A.z*C.y + A.w*C.x;

            int z0 = r0*Bc.x - r2*Bc.z;
            int z1 = r1*Bc.x - r3*Bc.z;
            int z2 = r2*Bc.x + r0*Bc.z;
            int z3 = r3*Bc.x + r1*Bc.z;

            bool nz = (b0 == 0);
            float f0 = nz ? (float)z0 : 0.0f;
            float f1 = nz ? (float)z1 : 0.0f;
            float f2 = nz ? (float)z2 : 0.0f;
            float f3 = nz ? (float)(-z3) : 0.0f;   // basis: c3_ref = -z3

            s_out[bsel[j]][gi] = make_float4(f0, f1, f2, f3);
        }
    }
    __syncthreads();

    // ---- store phase: lane-consecutive (b, gs) -> 32B contiguous chunks ----
    float4* out4 = (float4*)out;
    #pragma unroll
    for (int r = 0; r < 4; r++) {
        int idx = tid + r * 128;
        int b  = idx >> 1;
        int gs = idx & 1;
        out4[(size_t)b * G_DIM + g0 + gs] = s_out[b][gs];
    }
}

// ---------------------------------------------------------------------------
// Launch. Inputs identified BY SIZE (ordering-proof):
//   phases 32768 | params 2097152 | counts 2048 | param_vals 16384 | opp 32
// ---------------------------------------------------------------------------
extern "C" void kernel_launch(void* const* d_in, const int* in_sizes, int n_in,
                              void* d_out, int out_size) {
    const int* phases = nullptr;
    const int* params = nullptr;
    const int* counts = nullptr;
    const int* param_vals = nullptr;

    for (int i = 0; i < n_in; i++) {
        switch (in_sizes[i]) {
            case G_DIM * T_DIM:         phases     = (const int*)d_in[i]; break;
            case G_DIM * T_DIM * P_DIM: params     = (const int*)d_in[i]; break;
            case G_DIM:                 counts     = (const int*)d_in[i]; break;
            case B_DIM * P_DIM:         param_vals = (const int*)d_in[i]; break;
            default: break;  // one_plus_phases (32 floats) — unused
        }
    }

    init_kernel<<<12, 256>>>(param_vals);
    nodephases_main_kernel<<<G_DIM / 2, 128>>>(params, phases, counts,
                                               (float*)d_out);
}